// round 6
// baseline (speedup 1.0000x reference)
#include <cuda_runtime.h>
#include <cstdint>

#define VOCAB 50257
#define BATCH 4096
#define NBLK  592        // 148 SMs x 4 CTAs -> exactly one persistent wave
#define MAXROWS 7        // ceil(4096/592)

// Scratch (no device mallocs).
__device__ float g_cta_sum[NBLK];
__device__ unsigned int g_done = 0;   // self-resetting each launch

__global__ __launch_bounds__(256, 4) void ce_fused_kernel(
    const float* __restrict__ pred,
    const int* __restrict__ y,       // JAX x64-disabled => int32 labels
    float* __restrict__ out)
{
    const int tid = threadIdx.x;
    const int T = 256;
    const int wid = tid >> 5;
    const int lid = tid & 31;

    __shared__ float sm_part[MAXROWS][8];   // [row_k][warp] partials
    __shared__ float sm_loss[MAXROWS];
    __shared__ float sm[8];

    // ---- Barrier-free persistent mainloop: warps free-run across rows ----
    int k = 0;
    for (int row = blockIdx.x; row < BATCH; row += NBLK, k++) {
        const float* __restrict__ p = pred + (size_t)row * VOCAB;

        // Row base misalignment (in floats) relative to 16B; prologue to align.
        const int mis = (int)(((uintptr_t)p & 15u) >> 2);
        const int pro = (4 - mis) & 3;

        float s0 = 0.f, s1 = 0.f, s2 = 0.f, s3 = 0.f;

        if (tid < pro) s0 += __expf(p[tid]);

        const float4* __restrict__ p4 = (const float4*)(p + pro);
        const int n4 = (VOCAB - pro) >> 2;

        // 8 front-batched streaming LDG.128, then 32 EX2.
        int i = tid;
        for (; i + 7 * T < n4; i += 8 * T) {
            float4 v[8];
            #pragma unroll
            for (int u = 0; u < 8; u++)
                v[u] = __ldcs(&p4[i + u * T]);
            #pragma unroll
            for (int u = 0; u < 8; u++) {
                s0 += __expf(v[u].x);
                s1 += __expf(v[u].y);
                s2 += __expf(v[u].z);
                s3 += __expf(v[u].w);
            }
        }
        for (; i < n4; i += T) {
            float4 v = __ldcs(&p4[i]);
            s0 += __expf(v.x);
            s1 += __expf(v.y);
            s2 += __expf(v.z);
            s3 += __expf(v.w);
        }

        const int done = pro + (n4 << 2);
        const int tail = VOCAB - done;
        if (tid < tail) s1 += __expf(p[done + tid]);

        float s = (s0 + s1) + (s2 + s3);

        // Intra-warp reduce only; write private slot, NO barrier.
        #pragma unroll
        for (int o = 16; o > 0; o >>= 1)
            s += __shfl_xor_sync(0xffffffffu, s, o);
        if (lid == 0) sm_part[k][wid] = s;
    }

    __syncthreads();   // single barrier: all partials visible

    // Warp k finalizes row k (k < #rows of this CTA).
    {
        const int row = blockIdx.x + wid * NBLK;
        if (wid < MAXROWS && row < BATCH) {
            float v = (lid < 8) ? sm_part[wid][lid] : 0.f;
            #pragma unroll
            for (int o = 4; o > 0; o >>= 1)
                v += __shfl_xor_sync(0xffffffffu, v, o);
            if (lid == 0) {
                const int t = y[row];
                sm_loss[wid] = __logf(v) - pred[(size_t)row * VOCAB + t];
            }
        }
    }
    __syncthreads();

    __shared__ bool is_last;
    if (tid == 0) {
        float c = 0.f;
        #pragma unroll
        for (int j = 0; j < MAXROWS; j++)
            if (blockIdx.x + j * NBLK < BATCH) c += sm_loss[j];
        g_cta_sum[blockIdx.x] = c;
        __threadfence();
        unsigned int prev = atomicAdd(&g_done, 1u);
        is_last = (prev == (unsigned)(NBLK - 1));
    }
    __syncthreads();

    // Last CTA: reduce 592 per-CTA sums (fresh in L2).
    if (is_last) {
        float r = 0.f;
        for (int i = tid; i < NBLK; i += 256)
            r += g_cta_sum[i];

        #pragma unroll
        for (int o = 16; o > 0; o >>= 1)
            r += __shfl_xor_sync(0xffffffffu, r, o);
        if (lid == 0) sm[wid] = r;
        __syncthreads();
        if (tid == 0) {
            float tot = sm[0] + sm[1] + sm[2] + sm[3] + sm[4] + sm[5] + sm[6] + sm[7];
            out[0] = tot * (1.0f / BATCH);
            g_done = 0;   // reset for next launch / graph replay
        }
    }
}

extern "C" void kernel_launch(void* const* d_in, const int* in_sizes, int n_in,
                              void* d_out, int out_size)
{
    const float* pred = (const float*)d_in[0];
    const int* y = (const int*)d_in[1];
    float* out = (float*)d_out;

    ce_fused_kernel<<<NBLK, 256>>>(pred, y, out);
}

// round 7
// speedup vs baseline: 1.0622x; 1.0622x over previous
#include <cuda_runtime.h>
#include <cstdint>

#define VOCAB 50257
#define BATCH 4096
#define NBLK  592        // 148 SMs x 4 CTAs -> exactly one persistent wave
#define MAXROWS 7        // ceil(4096/592)

// Scratch (no device mallocs).
__device__ float g_cta_sum[NBLK];
__device__ unsigned int g_done = 0;   // self-resetting each launch

__global__ __launch_bounds__(256, 4) void ce_fused_kernel(
    const float* __restrict__ pred,
    const int* __restrict__ y,       // JAX x64-disabled => int32 labels
    float* __restrict__ out)
{
    const int tid = threadIdx.x;
    const int T = 256;
    const int wid = tid >> 5;
    const int lid = tid & 31;

    __shared__ float sm_part[MAXROWS][8];   // [row_k][warp] partials
    __shared__ float sm_loss[MAXROWS];
    __shared__ float sm[8];

    // ---- Persistent mainloop: ONE barrier per row keeps warps in lockstep ----
    int k = 0;
    for (int row = blockIdx.x; row < BATCH; row += NBLK, k++) {
        const float* __restrict__ p = pred + (size_t)row * VOCAB;

        // Row base misalignment (in floats) relative to 16B; prologue to align.
        const int mis = (int)(((uintptr_t)p & 15u) >> 2);
        const int pro = (4 - mis) & 3;

        float s0 = 0.f, s1 = 0.f, s2 = 0.f, s3 = 0.f;

        if (tid < pro) s0 += __expf(p[tid]);

        const float4* __restrict__ p4 = (const float4*)(p + pro);
        const int n4 = (VOCAB - pro) >> 2;

        // 8 front-batched streaming LDG.128, then 32 EX2.
        int i = tid;
        for (; i + 7 * T < n4; i += 8 * T) {
            float4 v[8];
            #pragma unroll
            for (int u = 0; u < 8; u++)
                v[u] = __ldcs(&p4[i + u * T]);
            #pragma unroll
            for (int u = 0; u < 8; u++) {
                s0 += __expf(v[u].x);
                s1 += __expf(v[u].y);
                s2 += __expf(v[u].z);
                s3 += __expf(v[u].w);
            }
        }
        for (; i < n4; i += T) {
            float4 v = __ldcs(&p4[i]);
            s0 += __expf(v.x);
            s1 += __expf(v.y);
            s2 += __expf(v.z);
            s3 += __expf(v.w);
        }

        const int done = pro + (n4 << 2);
        const int tail = VOCAB - done;
        if (tid < tail) s1 += __expf(p[done + tid]);

        float s = (s0 + s1) + (s2 + s3);

        // Intra-warp reduce; store to per-row slot; single barrier re-syncs warps.
        #pragma unroll
        for (int o = 16; o > 0; o >>= 1)
            s += __shfl_xor_sync(0xffffffffu, s, o);
        if (lid == 0) sm_part[k][wid] = s;
        __syncthreads();
    }
    // Last row's barrier above makes all partials visible here.

    // Warp k finalizes row k (k < #rows of this CTA).
    {
        const int row = blockIdx.x + wid * NBLK;
        if (wid < MAXROWS && row < BATCH) {
            float v = (lid < 8) ? sm_part[wid][lid] : 0.f;
            #pragma unroll
            for (int o = 4; o > 0; o >>= 1)
                v += __shfl_xor_sync(0xffffffffu, v, o);
            if (lid == 0) {
                const int t = y[row];
                sm_loss[wid] = __logf(v) - pred[(size_t)row * VOCAB + t];
            }
        }
    }
    __syncthreads();

    __shared__ bool is_last;
    if (tid == 0) {
        float c = 0.f;
        #pragma unroll
        for (int j = 0; j < MAXROWS; j++)
            if (blockIdx.x + j * NBLK < BATCH) c += sm_loss[j];
        g_cta_sum[blockIdx.x] = c;
        __threadfence();
        unsigned int prev = atomicAdd(&g_done, 1u);
        is_last = (prev == (unsigned)(NBLK - 1));
    }
    __syncthreads();

    // Last CTA: reduce 592 per-CTA sums (fresh in L2).
    if (is_last) {
        float r = 0.f;
        for (int i = tid; i < NBLK; i += 256)
            r += g_cta_sum[i];

        #pragma unroll
        for (int o = 16; o > 0; o >>= 1)
            r += __shfl_xor_sync(0xffffffffu, r, o);
        if (lid == 0) sm[wid] = r;
        __syncthreads();
        if (tid == 0) {
            float tot = sm[0] + sm[1] + sm[2] + sm[3] + sm[4] + sm[5] + sm[6] + sm[7];
            out[0] = tot * (1.0f / BATCH);
            g_done = 0;   // reset for next launch / graph replay
        }
    }
}

extern "C" void kernel_launch(void* const* d_in, const int* in_sizes, int n_in,
                              void* d_out, int out_size)
{
    const float* pred = (const float*)d_in[0];
    const int* y = (const int*)d_in[1];
    float* out = (float*)d_out;

    ce_fused_kernel<<<NBLK, 256>>>(pred, y, out);
}